// round 7
// baseline (speedup 1.0000x reference)
#include <cuda_runtime.h>
#include <cstdint>

// Fixed problem shape
#define NB 2048
#define ND 16384
#define RSPLIT 64
#define ROWS_PER (NB / RSPLIT)        // 32 rows per partial block
#define FIN_BLOCKS 32                 // 32 * 256 thr * 2 cols = 16384
#define SI_BLOCKS 64                  // 64 * 256 = 16384 cols
#define CHUNK_F4 1024                 // float4 per 16KB chunk
#define NCHUNK (ND / (CHUNK_F4 * 4))  // 4 chunks per row

// Scratch (__device__ globals; no allocation allowed)
__device__ float g_psum[RSPLIT * ND];
__device__ float g_psq [RSPLIT * ND];
__device__ float g_nmean[ND];
__device__ float g_nvar [ND];
__device__ float g_inv  [ND];
__device__ float g_varpart[FIN_BLOCKS];
__device__ float g_addend;
__device__ int   g_fcnt;              // zero-init; self-resetting

// ---------------------------------------------------------------------------
// Pass 1: per-(rowchunk, column) partial sum / sumsq.
// grid = (ND/1024, RSPLIT), block = 256, 4 cols/thread, 32 rows/block.
// ---------------------------------------------------------------------------
__global__ void __launch_bounds__(256) k_colstats_partial(const float* __restrict__ h) {
    const int c  = (blockIdx.x * 256 + threadIdx.x) * 4;
    const int r0 = blockIdx.y * ROWS_PER;
    float4 s = make_float4(0.f, 0.f, 0.f, 0.f);
    float4 q = make_float4(0.f, 0.f, 0.f, 0.f);
    const float4* hp = reinterpret_cast<const float4*>(h + (size_t)r0 * ND + c);
    const size_t stride4 = ND / 4;
#pragma unroll 8
    for (int r = 0; r < ROWS_PER; ++r) {
        float4 v = hp[(size_t)r * stride4];
        s.x += v.x;       s.y += v.y;       s.z += v.z;       s.w += v.w;
        q.x += v.x * v.x; q.y += v.y * v.y; q.z += v.z * v.z; q.w += v.w * v.w;
    }
    __stcs(reinterpret_cast<float4*>(g_psum + (size_t)blockIdx.y * ND + c), s);
    __stcs(reinterpret_cast<float4*>(g_psq  + (size_t)blockIdx.y * ND + c), q);
}

// ---------------------------------------------------------------------------
// Pass 2: finish stats -> new_mean, new_var; last block computes addend.
// grid = 32, block = 256, 2 cols/thread.
// ---------------------------------------------------------------------------
__global__ void __launch_bounds__(256) k_colstats_finish(const float* __restrict__ hmean,
                                                         const float* __restrict__ hvar) {
    const int c = (blockIdx.x * 256 + threadIdx.x) * 2;
    float2 s = make_float2(0.f, 0.f);
    float2 q = make_float2(0.f, 0.f);
#pragma unroll 8
    for (int i = 0; i < RSPLIT; ++i) {
        float2 a = __ldcs(reinterpret_cast<const float2*>(g_psum + (size_t)i * ND + c));
        float2 b = __ldcs(reinterpret_cast<const float2*>(g_psq  + (size_t)i * ND + c));
        s.x += a.x; s.y += a.y;
        q.x += b.x; q.y += b.y;
    }
    const float invB    = 1.0f / (float)NB;
    const float U       = 10.0f;
    const float inv11   = 1.0f / 11.0f;
    const float inv1p1  = 1.0f / 1.1f;
    const float invDen  = 1.0f / (U + 1.0f - invB);
    const float coefOld = U - invB;

    float2 hm = *reinterpret_cast<const float2*>(hmean + c);
    float2 hv = *reinterpret_cast<const float2*>(hvar  + c);

    float2 nm, nv;
    {
        float mu, var, d;
        mu = s.x * invB; var = q.x * invB - mu * mu; d = mu - hm.x;
        nv.x = (hv.x * coefOld + var + d * d * inv1p1) * invDen;
        nm.x = (hm.x * U + mu) * inv11;
        mu = s.y * invB; var = q.y * invB - mu * mu; d = mu - hm.y;
        nv.y = (hv.y * coefOld + var + d * d * inv1p1) * invDen;
        nm.y = (hm.y * U + mu) * inv11;
    }
    *reinterpret_cast<float2*>(g_nmean + c) = nm;
    *reinterpret_cast<float2*>(g_nvar  + c) = nv;

    __shared__ float sred[256];
    sred[threadIdx.x] = nv.x + nv.y;
    __syncthreads();
    for (int off = 128; off > 0; off >>= 1) {
        if (threadIdx.x < off) sred[threadIdx.x] += sred[threadIdx.x + off];
        __syncthreads();
    }

    __shared__ int is_last;
    if (threadIdx.x == 0) {
        g_varpart[blockIdx.x] = sred[0];
        __threadfence();
        int old = atomicAdd(&g_fcnt, 1);
        is_last = (old == FIN_BLOCKS - 1) ? 1 : 0;
    }
    __syncthreads();
    if (is_last && threadIdx.x < 32) {
        __threadfence();
        float v = g_varpart[threadIdx.x];   // FIN_BLOCKS == 32
#pragma unroll
        for (int off = 16; off > 0; off >>= 1)
            v += __shfl_down_sync(0xFFFFFFFFu, v, off);
        if (threadIdx.x == 0) {
            g_addend = (v / (float)ND) * 0.01f;
            g_fcnt = 0;                     // reset for next graph replay
        }
    }
}

// ---------------------------------------------------------------------------
// Pass 3: inv = 1/(new_var + addend). grid = 64, block = 256.
// ---------------------------------------------------------------------------
__global__ void __launch_bounds__(256) k_scalar_inv() {
    const float a = g_addend;
    const int c = blockIdx.x * 256 + threadIdx.x;
    g_inv[c] = 1.0f / (g_nvar[c] + a);
}

// ---------------------------------------------------------------------------
// Pass 4: one row per block. Reads h via LDG.128 (__ldcs); the copy is staged
// through shared memory (double-buffered 16KB chunks) and written to out via
// TMA bulk stores (cp.async.bulk) -> contiguous 16KB DRAM write bursts,
// decoupled from the read stream. Argmax tie semantics preserved (strict >,
// ascending columns per thread, lowest index in block reduce). Winner fixup
// is one STG after cp.async.bulk.wait_group 0.
// grid = NB, block = 256, 6 blocks/SM.
// ---------------------------------------------------------------------------
__device__ __forceinline__ float score_of(float hv, float m, float iv) {
    float d = __fadd_rn(hv, -m);
    return __fmul_rn(__fmul_rn(d, d), iv);
}

__global__ void __launch_bounds__(256, 6) k_punish(const float* __restrict__ h,
                                                   float* __restrict__ out) {
    __shared__ __align__(16) float4 sbuf[2][CHUNK_F4];   // 2 x 16KB
    __shared__ float sbest[256];
    __shared__ int   sidx[256];

    const int row = NB - 1 - blockIdx.x;
    const int tid = threadIdx.x;

    const float4* hrow = reinterpret_cast<const float4*>(h + (size_t)row * ND);
    float*        orow = out + (size_t)row * ND;
    const float4* m4p  = reinterpret_cast<const float4*>(g_nmean);
    const float4* i4p  = reinterpret_cast<const float4*>(g_inv);

    float best = -1.0f;   // scores >= 0
    int   bj   = tid;

#pragma unroll
    for (int c = 0; c < NCHUNK; ++c) {
        if (c >= 2) {
            // recycle buffer (c-2): wait until <=1 bulk group pending
            if (tid == 0)
                asm volatile("cp.async.bulk.wait_group 1;" ::: "memory");
            __syncthreads();
        }
        float4* buf = sbuf[c & 1];
#pragma unroll
        for (int it = 0; it < CHUNK_F4 / 256; ++it) {    // 4
            const int jloc = it * 256 + tid;
            const int j    = c * CHUNK_F4 + jloc;
            float4 hv = __ldcs(&hrow[j]);
            float4 m  = __ldg(&m4p[j]);
            float4 iv = __ldg(&i4p[j]);
            buf[jloc] = hv;
            float mx = fmaxf(fmaxf(score_of(hv.x, m.x, iv.x),
                                   score_of(hv.y, m.y, iv.y)),
                             fmaxf(score_of(hv.z, m.z, iv.z),
                                   score_of(hv.w, m.w, iv.w)));
            if (mx > best) { best = mx; bj = j; }
        }
        __syncthreads();      // all STS of this chunk visible
        if (tid == 0) {
            asm volatile("fence.proxy.async.shared::cta;" ::: "memory");
            uint32_t saddr;
            asm("{ .reg .u64 t; cvta.to.shared.u64 t, %1; cvt.u32.u64 %0, t; }"
                : "=r"(saddr) : "l"(buf));
            float* gdst = orow + c * (CHUNK_F4 * 4);
            asm volatile(
                "cp.async.bulk.global.shared::cta.bulk_group [%0], [%1], %2;"
                :: "l"(gdst), "r"(saddr), "r"((unsigned)(CHUNK_F4 * 16))
                : "memory");
            asm volatile("cp.async.bulk.commit_group;" ::: "memory");
        }
    }

    // Resolve winning element in the winning float4 (bitwise-identical
    // recompute; first match = lowest column, matching jnp.argmax ties).
    int bidx;
    {
        float4 hv = hrow[bj];          // same bits as scored
        float4 m  = __ldg(&m4p[bj]);
        float4 iv = __ldg(&i4p[bj]);
        float s0 = score_of(hv.x, m.x, iv.x);
        float s1 = score_of(hv.y, m.y, iv.y);
        float s2 = score_of(hv.z, m.z, iv.z);
        bidx = bj * 4 + ((s0 == best) ? 0 : (s1 == best) ? 1 : (s2 == best) ? 2 : 3);
    }

    sbest[tid] = best;
    sidx[tid]  = bidx;
    __syncthreads();
    for (int off = 128; off > 0; off >>= 1) {
        if (tid < off) {
            float ob = sbest[tid + off];
            int   oi = sidx[tid + off];
            if (ob > sbest[tid] || (ob == sbest[tid] && oi < sidx[tid])) {
                sbest[tid] = ob;
                sidx[tid]  = oi;
            }
        }
        __syncthreads();
    }
    if (tid == 0) {
        // all bulk stores of this row must land before the fixup overwrite
        asm volatile("cp.async.bulk.wait_group 0;" ::: "memory");
        int w = sidx[0];
        orow[w] = g_nmean[w];
    }
}

// ---------------------------------------------------------------------------
extern "C" void kernel_launch(void* const* d_in, const int* in_sizes, int n_in,
                              void* d_out, int out_size) {
    const float* h     = (const float*)d_in[0];
    const float* hmean = (const float*)d_in[1];
    const float* hvar  = (const float*)d_in[2];
    float* out = (float*)d_out;
    (void)in_sizes; (void)n_in; (void)out_size;

    dim3 g1(ND / (256 * 4), RSPLIT);
    k_colstats_partial<<<g1, 256>>>(h);
    k_colstats_finish<<<FIN_BLOCKS, 256>>>(hmean, hvar);
    k_scalar_inv<<<SI_BLOCKS, 256>>>();
    k_punish<<<NB, 256>>>(h, out);
}

// round 8
// speedup vs baseline: 1.4364x; 1.4364x over previous
#include <cuda_runtime.h>

// Fixed problem shape
#define NB 2048
#define ND 16384
#define RSPLIT 64
#define ROWS_PER (NB / RSPLIT)        // 32 rows per partial block
#define FIN_BLOCKS 32                 // 32 * 256 thr * 2 cols = 16384

// Scratch (__device__ globals; no allocation allowed)
__device__ float g_psum[RSPLIT * ND];
__device__ float g_psq [RSPLIT * ND];
__device__ float g_nmean[ND];
__device__ float g_nvar [ND];
__device__ float g_inv  [ND];
__device__ float g_varpart[FIN_BLOCKS];
__device__ float g_addend;
__device__ int   g_fcnt;              // zero-init; self-resetting
__device__ int   g_aflag;             // zero-init; self-resetting
__device__ int   g_done;              // zero-init; self-resetting

// ---------------------------------------------------------------------------
// Pass 1: per-(rowchunk, column) partial sum / sumsq.
// grid = (ND/1024, RSPLIT), block = 256, 4 cols/thread, 32 rows/block.
// (Measured: 23.5us, 74% DRAM.)
// ---------------------------------------------------------------------------
__global__ void __launch_bounds__(256) k_colstats_partial(const float* __restrict__ h) {
    const int c  = (blockIdx.x * 256 + threadIdx.x) * 4;
    const int r0 = blockIdx.y * ROWS_PER;
    float4 s = make_float4(0.f, 0.f, 0.f, 0.f);
    float4 q = make_float4(0.f, 0.f, 0.f, 0.f);
    const float4* hp = reinterpret_cast<const float4*>(h + (size_t)r0 * ND + c);
    const size_t stride4 = ND / 4;
#pragma unroll 8
    for (int r = 0; r < ROWS_PER; ++r) {
        float4 v = hp[(size_t)r * stride4];
        s.x += v.x;       s.y += v.y;       s.z += v.z;       s.w += v.w;
        q.x += v.x * v.x; q.y += v.y * v.y; q.z += v.z * v.z; q.w += v.w * v.w;
    }
    __stcs(reinterpret_cast<float4*>(g_psum + (size_t)blockIdx.y * ND + c), s);
    __stcs(reinterpret_cast<float4*>(g_psq  + (size_t)blockIdx.y * ND + c), q);
}

// ---------------------------------------------------------------------------
// Pass 2 (fused): finish stats -> new_mean, new_var; last block computes
// addend; ALL blocks (guaranteed co-resident: 32 blocks on 148 SMs, wave 1)
// spin for addend, then write their inv slice from registers. Self-resetting
// counters keep it graph-replay safe. grid = 32, block = 256, 2 cols/thread.
// ---------------------------------------------------------------------------
__global__ void __launch_bounds__(256) k_colstats_finish(const float* __restrict__ hmean,
                                                         const float* __restrict__ hvar) {
    const int c = (blockIdx.x * 256 + threadIdx.x) * 2;
    float2 s = make_float2(0.f, 0.f);
    float2 q = make_float2(0.f, 0.f);
#pragma unroll 8
    for (int i = 0; i < RSPLIT; ++i) {
        float2 a = __ldcs(reinterpret_cast<const float2*>(g_psum + (size_t)i * ND + c));
        float2 b = __ldcs(reinterpret_cast<const float2*>(g_psq  + (size_t)i * ND + c));
        s.x += a.x; s.y += a.y;
        q.x += b.x; q.y += b.y;
    }
    const float invB    = 1.0f / (float)NB;
    const float U       = 10.0f;
    const float inv11   = 1.0f / 11.0f;
    const float inv1p1  = 1.0f / 1.1f;
    const float invDen  = 1.0f / (U + 1.0f - invB);
    const float coefOld = U - invB;

    float2 hm = *reinterpret_cast<const float2*>(hmean + c);
    float2 hv = *reinterpret_cast<const float2*>(hvar  + c);

    float2 nm, nv;
    {
        float mu, var, d;
        mu = s.x * invB; var = q.x * invB - mu * mu; d = mu - hm.x;
        nv.x = (hv.x * coefOld + var + d * d * inv1p1) * invDen;
        nm.x = (hm.x * U + mu) * inv11;
        mu = s.y * invB; var = q.y * invB - mu * mu; d = mu - hm.y;
        nv.y = (hv.y * coefOld + var + d * d * inv1p1) * invDen;
        nm.y = (hm.y * U + mu) * inv11;
    }
    *reinterpret_cast<float2*>(g_nmean + c) = nm;
    *reinterpret_cast<float2*>(g_nvar  + c) = nv;

    // block partial of sum(new_var)
    __shared__ float sred[256];
    sred[threadIdx.x] = nv.x + nv.y;
    __syncthreads();
    for (int off = 128; off > 0; off >>= 1) {
        if (threadIdx.x < off) sred[threadIdx.x] += sred[threadIdx.x + off];
        __syncthreads();
    }

    __shared__ int is_last;
    if (threadIdx.x == 0) {
        g_varpart[blockIdx.x] = sred[0];
        __threadfence();
        int old = atomicAdd(&g_fcnt, 1);
        is_last = (old == FIN_BLOCKS - 1) ? 1 : 0;
    }
    __syncthreads();
    if (is_last && threadIdx.x < 32) {
        float v = g_varpart[threadIdx.x];   // FIN_BLOCKS == 32
#pragma unroll
        for (int off = 16; off > 0; off >>= 1)
            v += __shfl_down_sync(0xFFFFFFFFu, v, off);
        if (threadIdx.x == 0) {
            g_addend = (v / (float)ND) * 0.01f;
            __threadfence();
            atomicExch(&g_aflag, 1);
        }
    }

    // all blocks: wait for addend (co-resident spin), then write inv slice
    __shared__ float s_add;
    if (threadIdx.x == 0) {
        while (atomicAdd(&g_aflag, 0) == 0) {}
        __threadfence();
        s_add = g_addend;
    }
    __syncthreads();
    const float a = s_add;
    float2 iv;
    iv.x = 1.0f / (nv.x + a);
    iv.y = 1.0f / (nv.y + a);
    *reinterpret_cast<float2*>(g_inv + c) = iv;

    // self-reset for next graph replay (last block to finish)
    if (threadIdx.x == 0) {
        __threadfence();
        int old = atomicAdd(&g_done, 1);
        if (old == FIN_BLOCKS - 1) {
            g_fcnt  = 0;
            g_aflag = 0;
            g_done  = 0;
        }
    }
}

// ---------------------------------------------------------------------------
// Pass 3: per-row copy + argmax of (h-nm)^2 * inv + winner fixup.
// grid = NB, block = 256, one row per block, forward order. 4-way ILP,
// fmax-tree per float4, winner resolved by bitwise-identical recompute.
// (Measured: 47.9us, 58 regs — best punish so far.)
// ---------------------------------------------------------------------------
__device__ __forceinline__ float score_of(float hv, float m, float iv) {
    float d = __fadd_rn(hv, -m);
    return __fmul_rn(__fmul_rn(d, d), iv);
}

__global__ void __launch_bounds__(256) k_punish(const float* __restrict__ h,
                                                float* __restrict__ out) {
    const int row = blockIdx.x;
    const int tid = threadIdx.x;

    const float4* hrow = reinterpret_cast<const float4*>(h   + (size_t)row * ND);
    float4*       orow = reinterpret_cast<float4*>      (out + (size_t)row * ND);
    const float4* m4p  = reinterpret_cast<const float4*>(g_nmean);
    const float4* i4p  = reinterpret_cast<const float4*>(g_inv);

    float best = -1.0f;   // scores >= 0
    int   bj   = tid;     // winning float4 index (ascending per thread)

#pragma unroll
    for (int it = 0; it < ND / (256 * 4 * 4); ++it) {   // 4 iterations, 4 float4s
        const int jb = it * 1024 + tid;
        const int j0 = jb, j1 = jb + 256, j2 = jb + 512, j3 = jb + 768;

        float4 h0 = hrow[j0];
        float4 h1 = hrow[j1];
        float4 h2 = hrow[j2];
        float4 h3 = hrow[j3];
        float4 m0 = __ldg(&m4p[j0]);
        float4 m1 = __ldg(&m4p[j1]);
        float4 m2 = __ldg(&m4p[j2]);
        float4 m3 = __ldg(&m4p[j3]);
        float4 v0 = __ldg(&i4p[j0]);
        float4 v1 = __ldg(&i4p[j1]);
        float4 v2 = __ldg(&i4p[j2]);
        float4 v3 = __ldg(&i4p[j3]);

        __stcs(&orow[j0], h0);
        __stcs(&orow[j1], h1);
        __stcs(&orow[j2], h2);
        __stcs(&orow[j3], h3);

        float mx;
        mx = fmaxf(fmaxf(score_of(h0.x, m0.x, v0.x), score_of(h0.y, m0.y, v0.y)),
                   fmaxf(score_of(h0.z, m0.z, v0.z), score_of(h0.w, m0.w, v0.w)));
        if (mx > best) { best = mx; bj = j0; }
        mx = fmaxf(fmaxf(score_of(h1.x, m1.x, v1.x), score_of(h1.y, m1.y, v1.y)),
                   fmaxf(score_of(h1.z, m1.z, v1.z), score_of(h1.w, m1.w, v1.w)));
        if (mx > best) { best = mx; bj = j1; }
        mx = fmaxf(fmaxf(score_of(h2.x, m2.x, v2.x), score_of(h2.y, m2.y, v2.y)),
                   fmaxf(score_of(h2.z, m2.z, v2.z), score_of(h2.w, m2.w, v2.w)));
        if (mx > best) { best = mx; bj = j2; }
        mx = fmaxf(fmaxf(score_of(h3.x, m3.x, v3.x), score_of(h3.y, m3.y, v3.y)),
                   fmaxf(score_of(h3.z, m3.z, v3.z), score_of(h3.w, m3.w, v3.w)));
        if (mx > best) { best = mx; bj = j3; }
    }

    // Resolve winning element in the winning float4 (bitwise-identical
    // recompute; first match = lowest column, matching jnp.argmax ties).
    int bidx;
    {
        float4 hv = hrow[bj];           // L1 hit, same bits as scored
        float4 m  = __ldg(&m4p[bj]);
        float4 iv = __ldg(&i4p[bj]);
        float s0 = score_of(hv.x, m.x, iv.x);
        float s1 = score_of(hv.y, m.y, iv.y);
        float s2 = score_of(hv.z, m.z, iv.z);
        bidx = bj * 4 + ((s0 == best) ? 0 : (s1 == best) ? 1 : (s2 == best) ? 2 : 3);
    }

    __shared__ float sbest[256];
    __shared__ int   sidx[256];
    sbest[tid] = best;
    sidx[tid]  = bidx;
    __syncthreads();
    for (int off = 128; off > 0; off >>= 1) {
        if (tid < off) {
            float ob = sbest[tid + off];
            int   oi = sidx[tid + off];
            if (ob > sbest[tid] || (ob == sbest[tid] && oi < sidx[tid])) {
                sbest[tid] = ob;
                sidx[tid]  = oi;
            }
        }
        __syncthreads();
    }
    if (tid == 0) {
        int w = sidx[0];
        out[(size_t)row * ND + w] = g_nmean[w];
    }
}

// ---------------------------------------------------------------------------
extern "C" void kernel_launch(void* const* d_in, const int* in_sizes, int n_in,
                              void* d_out, int out_size) {
    const float* h     = (const float*)d_in[0];
    const float* hmean = (const float*)d_in[1];
    const float* hvar  = (const float*)d_in[2];
    float* out = (float*)d_out;
    (void)in_sizes; (void)n_in; (void)out_size;

    dim3 g1(ND / (256 * 4), RSPLIT);
    k_colstats_partial<<<g1, 256>>>(h);
    k_colstats_finish<<<FIN_BLOCKS, 256>>>(hmean, hvar);
    k_punish<<<NB, 256>>>(h, out);
}